// round 5
// baseline (speedup 1.0000x reference)
#include <cuda_runtime.h>

// out = noised + 0.1f * noise, elementwise over 50,331,648 fp32.
// HBM-bound: 604 MB traffic, target ~7 TB/s effective (~90 us).

__global__ void __launch_bounds__(256, 8)
gaussian_noise_axpy(const float4* __restrict__ noised,
                    const float4* __restrict__ noise,
                    float4* __restrict__ out,
                    int n4)
{
    // 2 float4 per thread, front-batched loads for MLP.
    int i0 = blockIdx.x * (blockDim.x * 2) + threadIdx.x;
    int i1 = i0 + blockDim.x;

    if (i1 < n4) {
        float4 a0 = noised[i0];
        float4 a1 = noised[i1];
        float4 b0 = noise[i0];
        float4 b1 = noise[i1];
        float4 r0, r1;
        r0.x = fmaf(0.1f, b0.x, a0.x);
        r0.y = fmaf(0.1f, b0.y, a0.y);
        r0.z = fmaf(0.1f, b0.z, a0.z);
        r0.w = fmaf(0.1f, b0.w, a0.w);
        r1.x = fmaf(0.1f, b1.x, a1.x);
        r1.y = fmaf(0.1f, b1.y, a1.y);
        r1.z = fmaf(0.1f, b1.z, a1.z);
        r1.w = fmaf(0.1f, b1.w, a1.w);
        out[i0] = r0;
        out[i1] = r1;
    } else if (i0 < n4) {
        float4 a0 = noised[i0];
        float4 b0 = noise[i0];
        float4 r0;
        r0.x = fmaf(0.1f, b0.x, a0.x);
        r0.y = fmaf(0.1f, b0.y, a0.y);
        r0.z = fmaf(0.1f, b0.z, a0.z);
        r0.w = fmaf(0.1f, b0.w, a0.w);
        out[i0] = r0;
    }
}

// Tail handler for n not divisible by 4 (defensive; current shape is divisible).
__global__ void gaussian_noise_tail(const float* __restrict__ noised,
                                    const float* __restrict__ noise,
                                    float* __restrict__ out,
                                    int start, int n)
{
    int i = start + blockIdx.x * blockDim.x + threadIdx.x;
    if (i < n) {
        out[i] = fmaf(0.1f, noise[i], noised[i]);
    }
}

extern "C" void kernel_launch(void* const* d_in, const int* in_sizes, int n_in,
                              void* d_out, int out_size)
{
    const float* noised = (const float*)d_in[0];
    const float* noise  = (const float*)d_in[1];
    float* out = (float*)d_out;
    int n = in_sizes[0];

    int n4 = n / 4;
    if (n4 > 0) {
        int threads = 256;
        int per_block = threads * 2;
        int blocks = (n4 + per_block - 1) / per_block;
        gaussian_noise_axpy<<<blocks, threads>>>(
            (const float4*)noised, (const float4*)noise, (float4*)out, n4);
    }
    int rem = n - n4 * 4;
    if (rem > 0) {
        gaussian_noise_tail<<<1, 256>>>(noised, noise, out, n4 * 4, n);
    }
}

// round 6
// speedup vs baseline: 1.0025x; 1.0025x over previous
#include <cuda_runtime.h>

// out = noised + 0.1f * noise, elementwise over 50,331,648 fp32.
// HBM-bound: 604 MB traffic. R5 baseline: 90.4us (DRAM 86.8%, 6876 GB/s).
// R6: streaming cache hints (.cs) on all three streams — zero reuse, so
// evict-first policy; probing whether L2 replacement pressure costs ~3-4%.

__global__ void __launch_bounds__(256, 8)
gaussian_noise_axpy(const float4* __restrict__ noised,
                    const float4* __restrict__ noise,
                    float4* __restrict__ out,
                    int n4)
{
    // 2 float4 per thread, front-batched loads for MLP.
    int i0 = blockIdx.x * (blockDim.x * 2) + threadIdx.x;
    int i1 = i0 + blockDim.x;

    if (i1 < n4) {
        float4 a0 = __ldcs(&noised[i0]);
        float4 a1 = __ldcs(&noised[i1]);
        float4 b0 = __ldcs(&noise[i0]);
        float4 b1 = __ldcs(&noise[i1]);
        float4 r0, r1;
        r0.x = fmaf(0.1f, b0.x, a0.x);
        r0.y = fmaf(0.1f, b0.y, a0.y);
        r0.z = fmaf(0.1f, b0.z, a0.z);
        r0.w = fmaf(0.1f, b0.w, a0.w);
        r1.x = fmaf(0.1f, b1.x, a1.x);
        r1.y = fmaf(0.1f, b1.y, a1.y);
        r1.z = fmaf(0.1f, b1.z, a1.z);
        r1.w = fmaf(0.1f, b1.w, a1.w);
        __stcs(&out[i0], r0);
        __stcs(&out[i1], r1);
    } else if (i0 < n4) {
        float4 a0 = __ldcs(&noised[i0]);
        float4 b0 = __ldcs(&noise[i0]);
        float4 r0;
        r0.x = fmaf(0.1f, b0.x, a0.x);
        r0.y = fmaf(0.1f, b0.y, a0.y);
        r0.z = fmaf(0.1f, b0.z, a0.z);
        r0.w = fmaf(0.1f, b0.w, a0.w);
        __stcs(&out[i0], r0);
    }
}

// Tail handler for n not divisible by 4 (defensive; current shape is divisible).
__global__ void gaussian_noise_tail(const float* __restrict__ noised,
                                    const float* __restrict__ noise,
                                    float* __restrict__ out,
                                    int start, int n)
{
    int i = start + blockIdx.x * blockDim.x + threadIdx.x;
    if (i < n) {
        out[i] = fmaf(0.1f, noise[i], noised[i]);
    }
}

extern "C" void kernel_launch(void* const* d_in, const int* in_sizes, int n_in,
                              void* d_out, int out_size)
{
    const float* noised = (const float*)d_in[0];
    const float* noise  = (const float*)d_in[1];
    float* out = (float*)d_out;
    int n = in_sizes[0];

    int n4 = n / 4;
    if (n4 > 0) {
        int threads = 256;
        int per_block = threads * 2;
        int blocks = (n4 + per_block - 1) / per_block;
        gaussian_noise_axpy<<<blocks, threads>>>(
            (const float4*)noised, (const float4*)noise, (float4*)out, n4);
    }
    int rem = n - n4 * 4;
    if (rem > 0) {
        gaussian_noise_tail<<<1, 256>>>(noised, noise, out, n4 * 4, n);
    }
}